// round 1
// baseline (speedup 1.0000x reference)
#include <cuda_runtime.h>
#include <cuda_bf16.h>
#include <math.h>

// Batched Kabsch RMSD:
//   per batch b: A = (P-pm)^T (C-cm)  (3x3), SVD singular values s1>=s2>=s3,
//   RMSD = sqrt( (Ep + Ec - 2*(s1+s2+sign(det A)*s3)) / N )
//   output = mean over batches.
//
// Kernel 1: one CTA per batch, streaming reduction of 17 scalars + closed-form
//           3x3 symmetric eigensolve (fp64) on thread 0 -> g_rmsd[b].
// Kernel 2: deterministic mean over g_rmsd -> d_out[0].

#define MAXB 8192

__device__ float g_rmsd[MAXB];

__device__ __forceinline__ float warp_sum(float v) {
    #pragma unroll
    for (int o = 16; o > 0; o >>= 1)
        v += __shfl_down_sync(0xffffffffu, v, o);
    return v;
}

__global__ __launch_bounds__(256, 4)
void kabsch_kernel(const float* __restrict__ P,
                   const float* __restrict__ Q,
                   int npts)
{
    const int b = blockIdx.x;
    const float4* pb = reinterpret_cast<const float4*>(P + (size_t)b * npts * 3);
    const float4* qb = reinterpret_cast<const float4*>(Q + (size_t)b * npts * 3);
    const int ngroups = (npts * 3) / 12;   // 4 points per group (3 x float4)

    // acc: [0..2]=sum_p, [3..5]=sum_q, [6]=sum|p|^2, [7]=sum|q|^2,
    //      [8..16]=sum p_a*q_b row-major (a fast over rows)
    float acc[17];
    #pragma unroll
    for (int i = 0; i < 17; i++) acc[i] = 0.f;

    for (int g = threadIdx.x; g < ngroups; g += blockDim.x) {
        float4 pA = pb[3*g+0], pB = pb[3*g+1], pC = pb[3*g+2];
        float4 qA = qb[3*g+0], qB = qb[3*g+1], qC = qb[3*g+2];

        float px[4] = {pA.x, pA.w, pB.z, pC.y};
        float py[4] = {pA.y, pB.x, pB.w, pC.z};
        float pz[4] = {pA.z, pB.y, pC.x, pC.w};
        float qx[4] = {qA.x, qA.w, qB.z, qC.y};
        float qy[4] = {qA.y, qB.x, qB.w, qC.z};
        float qz[4] = {qA.z, qB.y, qC.x, qC.w};

        #pragma unroll
        for (int k = 0; k < 4; k++) {
            acc[0] += px[k]; acc[1] += py[k]; acc[2] += pz[k];
            acc[3] += qx[k]; acc[4] += qy[k]; acc[5] += qz[k];
            acc[6]  = fmaf(px[k], px[k], fmaf(py[k], py[k], fmaf(pz[k], pz[k], acc[6])));
            acc[7]  = fmaf(qx[k], qx[k], fmaf(qy[k], qy[k], fmaf(qz[k], qz[k], acc[7])));
            acc[8]  = fmaf(px[k], qx[k], acc[8]);
            acc[9]  = fmaf(px[k], qy[k], acc[9]);
            acc[10] = fmaf(px[k], qz[k], acc[10]);
            acc[11] = fmaf(py[k], qx[k], acc[11]);
            acc[12] = fmaf(py[k], qy[k], acc[12]);
            acc[13] = fmaf(py[k], qz[k], acc[13]);
            acc[14] = fmaf(pz[k], qx[k], acc[14]);
            acc[15] = fmaf(pz[k], qy[k], acc[15]);
            acc[16] = fmaf(pz[k], qz[k], acc[16]);
        }
    }

    __shared__ float sred[8][17];
    const int lane = threadIdx.x & 31;
    const int wid  = threadIdx.x >> 5;

    #pragma unroll
    for (int i = 0; i < 17; i++) {
        float v = warp_sum(acc[i]);
        if (lane == 0) sred[wid][i] = v;
    }
    __syncthreads();

    if (wid == 0) {
        float fin[17];
        #pragma unroll
        for (int i = 0; i < 17; i++) {
            float v = (lane < 8) ? sred[lane][i] : 0.f;
            v += __shfl_down_sync(0xffffffffu, v, 4);
            v += __shfl_down_sync(0xffffffffu, v, 2);
            v += __shfl_down_sync(0xffffffffu, v, 1);
            fin[i] = v;   // valid on lane 0
        }

        if (lane == 0) {
            const double n = (double)npts;
            double pm0 = fin[0] / n, pm1 = fin[1] / n, pm2 = fin[2] / n;
            double qm0 = fin[3] / n, qm1 = fin[4] / n, qm2 = fin[5] / n;
            double Ep = (double)fin[6] - n * (pm0*pm0 + pm1*pm1 + pm2*pm2);
            double Ec = (double)fin[7] - n * (qm0*qm0 + qm1*qm1 + qm2*qm2);

            // centered cross-covariance A[a][b] = sum p_a q_b - n*pm_a*qm_b
            double A0 = (double)fin[8]  - n * pm0 * qm0;
            double A1 = (double)fin[9]  - n * pm0 * qm1;
            double A2 = (double)fin[10] - n * pm0 * qm2;
            double A3 = (double)fin[11] - n * pm1 * qm0;
            double A4 = (double)fin[12] - n * pm1 * qm1;
            double A5 = (double)fin[13] - n * pm1 * qm2;
            double A6 = (double)fin[14] - n * pm2 * qm0;
            double A7 = (double)fin[15] - n * pm2 * qm1;
            double A8 = (double)fin[16] - n * pm2 * qm2;

            double detA = A0 * (A4 * A8 - A5 * A7)
                        - A1 * (A3 * A8 - A5 * A6)
                        + A2 * (A3 * A7 - A4 * A6);

            // M = A^T A (symmetric PSD)
            double m00 = A0*A0 + A3*A3 + A6*A6;
            double m01 = A0*A1 + A3*A4 + A6*A7;
            double m02 = A0*A2 + A3*A5 + A6*A8;
            double m11 = A1*A1 + A4*A4 + A7*A7;
            double m12 = A1*A2 + A4*A5 + A7*A8;
            double m22 = A2*A2 + A5*A5 + A8*A8;

            // closed-form eigenvalues of symmetric 3x3 (trigonometric)
            double q  = (m00 + m11 + m22) / 3.0;
            double p1 = m01*m01 + m02*m02 + m12*m12;
            double p2 = (m00-q)*(m00-q) + (m11-q)*(m11-q) + (m22-q)*(m22-q) + 2.0*p1;
            double e1, e2, e3;
            if (p2 < 1e-300) {
                e1 = e2 = e3 = q;
            } else {
                double pp = sqrt(p2 / 6.0);
                double inv = 1.0 / pp;
                double b00 = (m00 - q) * inv, b11 = (m11 - q) * inv, b22 = (m22 - q) * inv;
                double b01 = m01 * inv, b02 = m02 * inv, b12 = m12 * inv;
                double detB = b00 * (b11 * b22 - b12 * b12)
                            - b01 * (b01 * b22 - b12 * b02)
                            + b02 * (b01 * b12 - b11 * b02);
                double r = detB * 0.5;
                r = fmin(1.0, fmax(-1.0, r));
                double phi = acos(r) / 3.0;
                e1 = q + 2.0 * pp * cos(phi);                         // largest
                e3 = q + 2.0 * pp * cos(phi + 2.0943951023931953);    // smallest
                e2 = 3.0 * q - e1 - e3;
            }
            double s1 = sqrt(fmax(e1, 0.0));
            double s2 = sqrt(fmax(e2, 0.0));
            double s3 = sqrt(fmax(e3, 0.0));
            double tr = s1 + s2 + ((detA >= 0.0) ? s3 : -s3);

            double msd = fmax(0.0, (Ep + Ec - 2.0 * tr) / n);
            g_rmsd[b] = (float)sqrt(msd);
        }
    }
}

__global__ __launch_bounds__(256)
void mean_kernel(float* __restrict__ out, int B)
{
    float s = 0.f;
    for (int i = threadIdx.x; i < B; i += blockDim.x)
        s += g_rmsd[i];

    __shared__ float sm[8];
    const int lane = threadIdx.x & 31;
    const int wid  = threadIdx.x >> 5;
    s = warp_sum(s);
    if (lane == 0) sm[wid] = s;
    __syncthreads();
    if (wid == 0) {
        float v = (lane < 8) ? sm[lane] : 0.f;
        v += __shfl_down_sync(0xffffffffu, v, 4);
        v += __shfl_down_sync(0xffffffffu, v, 2);
        v += __shfl_down_sync(0xffffffffu, v, 1);
        if (lane == 0) out[0] = v / (float)B;
    }
}

extern "C" void kernel_launch(void* const* d_in, const int* in_sizes, int n_in,
                              void* d_out, int out_size)
{
    const float* p = (const float*)d_in[0];   // coords_pred [B, N, 3]
    const float* c = (const float*)d_in[1];   // coords      [B, N, 3]
    const int npts = 2048;
    const int B = in_sizes[0] / (npts * 3);

    kabsch_kernel<<<B, 256>>>(p, c, npts);
    mean_kernel<<<1, 256>>>((float*)d_out, B);
}

// round 2
// speedup vs baseline: 1.7015x; 1.7015x over previous
#include <cuda_runtime.h>
#include <cuda_bf16.h>
#include <math.h>

// Batched Kabsch RMSD, 3-kernel pipeline:
//  K1 stream:  [B,N,3] x2 fp32 -> per-batch 17 reduced scalars (pure fp32 streaming)
//  K2 solve:   per-batch fp64 closed-form 3x3 eigensolve -> rmsd[b]
//  K3 mean:    deterministic mean over B rmsds -> out[0]

#define MAXB 8192

__device__ float g_part[MAXB * 17];
__device__ float g_rmsd[MAXB];

__device__ __forceinline__ float warp_sum(float v) {
    #pragma unroll
    for (int o = 16; o > 0; o >>= 1)
        v += __shfl_down_sync(0xffffffffu, v, o);
    return v;
}

// ---------------- K1: streaming reduction ----------------
// grid = B, block = 512. Each thread owns exactly one group of 4 points
// (3 float4 from each array, contiguous 48B), so all 6 LDG.128 are
// independent and front-batched. No fp64 anywhere in this kernel.
__global__ __launch_bounds__(512)
void stream_kernel(const float* __restrict__ P,
                   const float* __restrict__ Q)
{
    const int b = blockIdx.x;
    const int g = threadIdx.x;                      // 0..511 groups
    const float4* pb = reinterpret_cast<const float4*>(P + (size_t)b * 6144);
    const float4* qb = reinterpret_cast<const float4*>(Q + (size_t)b * 6144);

    float4 pA = pb[3*g+0], pB = pb[3*g+1], pC = pb[3*g+2];
    float4 qA = qb[3*g+0], qB = qb[3*g+1], qC = qb[3*g+2];

    float px[4] = {pA.x, pA.w, pB.z, pC.y};
    float py[4] = {pA.y, pB.x, pB.w, pC.z};
    float pz[4] = {pA.z, pB.y, pC.x, pC.w};
    float qx[4] = {qA.x, qA.w, qB.z, qC.y};
    float qy[4] = {qA.y, qB.x, qB.w, qC.z};
    float qz[4] = {qA.z, qB.y, qC.x, qC.w};

    float acc[17];
    #pragma unroll
    for (int i = 0; i < 17; i++) acc[i] = 0.f;

    #pragma unroll
    for (int k = 0; k < 4; k++) {
        acc[0] += px[k]; acc[1] += py[k]; acc[2] += pz[k];
        acc[3] += qx[k]; acc[4] += qy[k]; acc[5] += qz[k];
        acc[6]  = fmaf(px[k], px[k], fmaf(py[k], py[k], fmaf(pz[k], pz[k], acc[6])));
        acc[7]  = fmaf(qx[k], qx[k], fmaf(qy[k], qy[k], fmaf(qz[k], qz[k], acc[7])));
        acc[8]  = fmaf(px[k], qx[k], acc[8]);
        acc[9]  = fmaf(px[k], qy[k], acc[9]);
        acc[10] = fmaf(px[k], qz[k], acc[10]);
        acc[11] = fmaf(py[k], qx[k], acc[11]);
        acc[12] = fmaf(py[k], qy[k], acc[12]);
        acc[13] = fmaf(py[k], qz[k], acc[13]);
        acc[14] = fmaf(pz[k], qx[k], acc[14]);
        acc[15] = fmaf(pz[k], qy[k], acc[15]);
        acc[16] = fmaf(pz[k], qz[k], acc[16]);
    }

    __shared__ float sred[16][17];
    const int lane = threadIdx.x & 31;
    const int wid  = threadIdx.x >> 5;              // 0..15

    #pragma unroll
    for (int i = 0; i < 17; i++) {
        float v = warp_sum(acc[i]);
        if (lane == 0) sred[wid][i] = v;
    }
    __syncthreads();

    if (wid == 0) {
        #pragma unroll
        for (int i = 0; i < 17; i++) {
            float v = (lane < 16) ? sred[lane][i] : 0.f;
            v += __shfl_down_sync(0xffffffffu, v, 8);
            v += __shfl_down_sync(0xffffffffu, v, 4);
            v += __shfl_down_sync(0xffffffffu, v, 2);
            v += __shfl_down_sync(0xffffffffu, v, 1);
            if (lane == 0) g_part[b * 17 + i] = v;
        }
    }
}

// ---------------- K2: per-batch fp64 eigensolve ----------------
__global__ __launch_bounds__(256)
void solve_kernel(int B, int npts)
{
    const int b = blockIdx.x * blockDim.x + threadIdx.x;
    if (b >= B) return;

    float fin[17];
    #pragma unroll
    for (int i = 0; i < 17; i++) fin[i] = g_part[b * 17 + i];

    const double n = (double)npts;
    double pm0 = fin[0] / n, pm1 = fin[1] / n, pm2 = fin[2] / n;
    double qm0 = fin[3] / n, qm1 = fin[4] / n, qm2 = fin[5] / n;
    double Ep = (double)fin[6] - n * (pm0*pm0 + pm1*pm1 + pm2*pm2);
    double Ec = (double)fin[7] - n * (qm0*qm0 + qm1*qm1 + qm2*qm2);

    double A0 = (double)fin[8]  - n * pm0 * qm0;
    double A1 = (double)fin[9]  - n * pm0 * qm1;
    double A2 = (double)fin[10] - n * pm0 * qm2;
    double A3 = (double)fin[11] - n * pm1 * qm0;
    double A4 = (double)fin[12] - n * pm1 * qm1;
    double A5 = (double)fin[13] - n * pm1 * qm2;
    double A6 = (double)fin[14] - n * pm2 * qm0;
    double A7 = (double)fin[15] - n * pm2 * qm1;
    double A8 = (double)fin[16] - n * pm2 * qm2;

    double detA = A0 * (A4 * A8 - A5 * A7)
                - A1 * (A3 * A8 - A5 * A6)
                + A2 * (A3 * A7 - A4 * A6);

    double m00 = A0*A0 + A3*A3 + A6*A6;
    double m01 = A0*A1 + A3*A4 + A6*A7;
    double m02 = A0*A2 + A3*A5 + A6*A8;
    double m11 = A1*A1 + A4*A4 + A7*A7;
    double m12 = A1*A2 + A4*A5 + A7*A8;
    double m22 = A2*A2 + A5*A5 + A8*A8;

    double q  = (m00 + m11 + m22) / 3.0;
    double p1 = m01*m01 + m02*m02 + m12*m12;
    double p2 = (m00-q)*(m00-q) + (m11-q)*(m11-q) + (m22-q)*(m22-q) + 2.0*p1;
    double e1, e2, e3;
    if (p2 < 1e-300) {
        e1 = e2 = e3 = q;
    } else {
        double pp = sqrt(p2 / 6.0);
        double inv = 1.0 / pp;
        double b00 = (m00 - q) * inv, b11 = (m11 - q) * inv, b22 = (m22 - q) * inv;
        double b01 = m01 * inv, b02 = m02 * inv, b12 = m12 * inv;
        double detB = b00 * (b11 * b22 - b12 * b12)
                    - b01 * (b01 * b22 - b12 * b02)
                    + b02 * (b01 * b12 - b11 * b02);
        double r = detB * 0.5;
        r = fmin(1.0, fmax(-1.0, r));
        double phi = acos(r) / 3.0;
        e1 = q + 2.0 * pp * cos(phi);                         // largest
        e3 = q + 2.0 * pp * cos(phi + 2.0943951023931953);    // smallest
        e2 = 3.0 * q - e1 - e3;
    }
    double s1 = sqrt(fmax(e1, 0.0));
    double s2 = sqrt(fmax(e2, 0.0));
    double s3 = sqrt(fmax(e3, 0.0));
    double tr = s1 + s2 + ((detA >= 0.0) ? s3 : -s3);

    double msd = fmax(0.0, (Ep + Ec - 2.0 * tr) / n);
    g_rmsd[b] = (float)sqrt(msd);
}

// ---------------- K3: deterministic mean ----------------
__global__ __launch_bounds__(1024)
void mean_kernel(float* __restrict__ out, int B)
{
    float s = 0.f;
    for (int i = threadIdx.x; i < B; i += blockDim.x)
        s += g_rmsd[i];

    __shared__ float sm[32];
    const int lane = threadIdx.x & 31;
    const int wid  = threadIdx.x >> 5;
    s = warp_sum(s);
    if (lane == 0) sm[wid] = s;
    __syncthreads();
    if (wid == 0) {
        float v = (lane < (int)(blockDim.x >> 5)) ? sm[lane] : 0.f;
        v = warp_sum(v);
        if (lane == 0) out[0] = v / (float)B;
    }
}

extern "C" void kernel_launch(void* const* d_in, const int* in_sizes, int n_in,
                              void* d_out, int out_size)
{
    const float* p = (const float*)d_in[0];   // coords_pred [B, N, 3]
    const float* c = (const float*)d_in[1];   // coords      [B, N, 3]
    const int npts = 2048;
    const int B = in_sizes[0] / (npts * 3);

    stream_kernel<<<B, 512>>>(p, c);
    solve_kernel<<<(B + 255) / 256, 256>>>(B, npts);
    mean_kernel<<<1, 1024>>>((float*)d_out, B);
}

// round 3
// speedup vs baseline: 3.0284x; 1.7799x over previous
#include <cuda_runtime.h>
#include <cuda_bf16.h>
#include <math.h>

// Batched Kabsch RMSD:
//  K1: warp-per-batch streaming reduction -> 17 scalars per batch (pure fp32,
//      no block barriers, reduce amortized over 16 load iterations per thread)
//  K2: fp32 closed-form 3x3 eigensolve per batch + per-CTA rmsd partial sum
//  K3: tiny final sum of 16 partials -> mean

#define MAXB 8192
#define NPTS 2048
#define K2_BLOCK 256

__device__ float g_part[MAXB * 17];
__device__ float g_psum[MAXB / K2_BLOCK];

__device__ __forceinline__ float warp_sum(float v) {
    #pragma unroll
    for (int o = 16; o > 0; o >>= 1)
        v += __shfl_down_sync(0xffffffffu, v, o);
    return v;
}

// ---------------- K1: warp-per-batch streaming ----------------
// block = 256 (8 warps), grid = B/8. Warp w handles batch b.
// Per batch: 1536 float4 per array; per lane: 16 iterations x (3+3) LDG.128.
__global__ __launch_bounds__(256)
void stream_kernel(const float* __restrict__ P,
                   const float* __restrict__ Q)
{
    const int lane = threadIdx.x & 31;
    const int wid  = threadIdx.x >> 5;
    const int b    = blockIdx.x * 8 + wid;

    const float4* pb = reinterpret_cast<const float4*>(P + (size_t)b * (NPTS * 3));
    const float4* qb = reinterpret_cast<const float4*>(Q + (size_t)b * (NPTS * 3));

    // acc: [0..2]=sum_p, [3..5]=sum_q, [6]=sum|p|^2, [7]=sum|q|^2,
    //      [8..16]=sum p_a*q_b (row-major)
    float acc[17];
    #pragma unroll
    for (int i = 0; i < 17; i++) acc[i] = 0.f;

    #pragma unroll 2
    for (int j = 0; j < 16; j++) {
        const int g = j * 32 + lane;          // group of 4 points
        float4 pA = pb[3*g+0], pB = pb[3*g+1], pC = pb[3*g+2];
        float4 qA = qb[3*g+0], qB = qb[3*g+1], qC = qb[3*g+2];

        float px[4] = {pA.x, pA.w, pB.z, pC.y};
        float py[4] = {pA.y, pB.x, pB.w, pC.z};
        float pz[4] = {pA.z, pB.y, pC.x, pC.w};
        float qx[4] = {qA.x, qA.w, qB.z, qC.y};
        float qy[4] = {qA.y, qB.x, qB.w, qC.z};
        float qz[4] = {qA.z, qB.y, qC.x, qC.w};

        #pragma unroll
        for (int k = 0; k < 4; k++) {
            acc[0] += px[k]; acc[1] += py[k]; acc[2] += pz[k];
            acc[3] += qx[k]; acc[4] += qy[k]; acc[5] += qz[k];
            acc[6]  = fmaf(px[k], px[k], fmaf(py[k], py[k], fmaf(pz[k], pz[k], acc[6])));
            acc[7]  = fmaf(qx[k], qx[k], fmaf(qy[k], qy[k], fmaf(qz[k], qz[k], acc[7])));
            acc[8]  = fmaf(px[k], qx[k], acc[8]);
            acc[9]  = fmaf(px[k], qy[k], acc[9]);
            acc[10] = fmaf(px[k], qz[k], acc[10]);
            acc[11] = fmaf(py[k], qx[k], acc[11]);
            acc[12] = fmaf(py[k], qy[k], acc[12]);
            acc[13] = fmaf(py[k], qz[k], acc[13]);
            acc[14] = fmaf(pz[k], qx[k], acc[14]);
            acc[15] = fmaf(pz[k], qy[k], acc[15]);
            acc[16] = fmaf(pz[k], qz[k], acc[16]);
        }
    }

    // warp-local reduce, lane 0 stores
    #pragma unroll
    for (int i = 0; i < 17; i++) {
        float v = warp_sum(acc[i]);
        if (lane == 0) g_part[b * 17 + i] = v;
    }
}

// ---------------- K2: fp32 eigensolve + per-CTA partial sum ----------------
__global__ __launch_bounds__(K2_BLOCK)
void solve_kernel(int B)
{
    const int b = blockIdx.x * blockDim.x + threadIdx.x;

    float r_out = 0.f;
    if (b < B) {
        float fin[17];
        #pragma unroll
        for (int i = 0; i < 17; i++) fin[i] = g_part[b * 17 + i];

        const float n = (float)NPTS;
        const float invn = 1.0f / n;
        float pm0 = fin[0] * invn, pm1 = fin[1] * invn, pm2 = fin[2] * invn;
        float qm0 = fin[3] * invn, qm1 = fin[4] * invn, qm2 = fin[5] * invn;
        float Ep = fin[6] - n * (pm0*pm0 + pm1*pm1 + pm2*pm2);
        float Ec = fin[7] - n * (qm0*qm0 + qm1*qm1 + qm2*qm2);

        float A0 = fin[8]  - n * pm0 * qm0;
        float A1 = fin[9]  - n * pm0 * qm1;
        float A2 = fin[10] - n * pm0 * qm2;
        float A3 = fin[11] - n * pm1 * qm0;
        float A4 = fin[12] - n * pm1 * qm1;
        float A5 = fin[13] - n * pm1 * qm2;
        float A6 = fin[14] - n * pm2 * qm0;
        float A7 = fin[15] - n * pm2 * qm1;
        float A8 = fin[16] - n * pm2 * qm2;

        float detA = A0 * (A4 * A8 - A5 * A7)
                   - A1 * (A3 * A8 - A5 * A6)
                   + A2 * (A3 * A7 - A4 * A6);

        // M = A^T A (symmetric PSD)
        float m00 = A0*A0 + A3*A3 + A6*A6;
        float m01 = A0*A1 + A3*A4 + A6*A7;
        float m02 = A0*A2 + A3*A5 + A6*A8;
        float m11 = A1*A1 + A4*A4 + A7*A7;
        float m12 = A1*A2 + A4*A5 + A7*A8;
        float m22 = A2*A2 + A5*A5 + A8*A8;

        float q  = (m00 + m11 + m22) * (1.0f/3.0f);
        float p1 = m01*m01 + m02*m02 + m12*m12;
        float p2 = (m00-q)*(m00-q) + (m11-q)*(m11-q) + (m22-q)*(m22-q) + 2.0f*p1;
        float e1, e2, e3;
        if (p2 < 1e-30f) {
            e1 = e2 = e3 = q;
        } else {
            float pp = sqrtf(p2 * (1.0f/6.0f));
            float inv = 1.0f / pp;
            float b00 = (m00 - q) * inv, b11 = (m11 - q) * inv, b22 = (m22 - q) * inv;
            float b01 = m01 * inv, b02 = m02 * inv, b12 = m12 * inv;
            float detB = b00 * (b11 * b22 - b12 * b12)
                       - b01 * (b01 * b22 - b12 * b02)
                       + b02 * (b01 * b12 - b11 * b02);
            float r = detB * 0.5f;
            r = fminf(1.0f, fmaxf(-1.0f, r));
            float phi = acosf(r) * (1.0f/3.0f);
            e1 = q + 2.0f * pp * cosf(phi);                       // largest
            e3 = q + 2.0f * pp * cosf(phi + 2.0943951023931953f); // smallest
            e2 = 3.0f * q - e1 - e3;
        }
        float s1 = sqrtf(fmaxf(e1, 0.f));
        float s2 = sqrtf(fmaxf(e2, 0.f));
        float s3 = sqrtf(fmaxf(e3, 0.f));
        float tr = s1 + s2 + ((detA >= 0.f) ? s3 : -s3);

        float msd = fmaxf(0.f, (Ep + Ec - 2.0f * tr) / n);
        r_out = sqrtf(msd);
    }

    // block-reduce rmsd partial sum
    __shared__ float sm[K2_BLOCK / 32];
    const int lane = threadIdx.x & 31;
    const int wid  = threadIdx.x >> 5;
    float s = warp_sum(r_out);
    if (lane == 0) sm[wid] = s;
    __syncthreads();
    if (wid == 0) {
        float v = (lane < (K2_BLOCK / 32)) ? sm[lane] : 0.f;
        v = warp_sum(v);
        if (lane == 0) g_psum[blockIdx.x] = v;
    }
}

// ---------------- K3: final mean over partials ----------------
__global__ void mean_kernel(float* __restrict__ out, int nparts, int B)
{
    float s = (threadIdx.x < nparts) ? g_psum[threadIdx.x] : 0.f;
    s = warp_sum(s);
    if (threadIdx.x == 0) out[0] = s / (float)B;
}

extern "C" void kernel_launch(void* const* d_in, const int* in_sizes, int n_in,
                              void* d_out, int out_size)
{
    const float* p = (const float*)d_in[0];   // coords_pred [B, N, 3]
    const float* c = (const float*)d_in[1];   // coords      [B, N, 3]
    const int B = in_sizes[0] / (NPTS * 3);

    stream_kernel<<<B / 8, 256>>>(p, c);
    const int nparts = (B + K2_BLOCK - 1) / K2_BLOCK;
    solve_kernel<<<nparts, K2_BLOCK>>>(B);
    mean_kernel<<<1, 32>>>((float*)d_out, nparts, B);
}